// round 16
// baseline (speedup 1.0000x reference)
#include <cuda_runtime.h>
#include <cuda_fp16.h>

#define FULL 0xffffffffu
typedef unsigned long long ull;
typedef unsigned int uint;

__device__ __forceinline__ float relu_(float v) { return fmaxf(v, 0.0f); }

__device__ __forceinline__ ull fadd2(ull a, ull b) {
    ull d; asm("add.rn.f32x2 %0, %1, %2;" : "=l"(d) : "l"(a), "l"(b)); return d;
}
__device__ __forceinline__ ull pk2(float lo, float hi) {
    ull r; asm("mov.b64 %0, {%1, %2};" : "=l"(r) : "f"(lo), "f"(hi)); return r;
}
__device__ __forceinline__ void upk2(ull v, float& lo, float& hi) {
    asm("mov.b64 {%0, %1}, %2;" : "=f"(lo), "=f"(hi) : "l"(v));
}

// fp16x2 pack (e0 -> lower 16 bits)
__device__ __forceinline__ uint pack_f16(float e0, float e1) {
    __half2 h = __floats2half2_rn(e0, e1);
    return *reinterpret_cast<uint*>(&h);
}
// relu in the fp16x2 domain
__device__ __forceinline__ uint hrelu2(uint v) {
    uint r; asm("max.f16x2 %0, %1, %2;" : "=r"(r) : "r"(v), "r"(0u)); return r;
}
__device__ __forceinline__ uint packrelu_f16(float e0, float e1) {
    return hrelu2(pack_f16(e0, e1));
}

// m16n8k16 fp16 MMA, in-place fp32 accumulate.
__device__ __forceinline__ void mma_f16(float4& d, uint a0, uint a1, uint a2, uint a3,
                                        uint b0, uint b1) {
    asm volatile(
        "mma.sync.aligned.m16n8k16.row.col.f32.f16.f16.f32 "
        "{%0,%1,%2,%3}, {%4,%5,%6,%7}, {%8,%9}, {%0,%1,%2,%3};"
        : "+f"(d.x), "+f"(d.y), "+f"(d.z), "+f"(d.w)
        : "r"(a0), "r"(a1), "r"(a2), "r"(a3), "r"(b0), "r"(b1));
}
// m16n8k16 fp16 MMA, SEPARATE C operand: D = A*B + C.
__device__ __forceinline__ float4 mma_f16_c(uint a0, uint a1, uint a2, uint a3,
                                            uint b0, uint b1,
                                            float c0, float c1, float c2, float c3) {
    float4 d;
    asm volatile(
        "mma.sync.aligned.m16n8k16.row.col.f32.f16.f16.f32 "
        "{%0,%1,%2,%3}, {%4,%5,%6,%7}, {%8,%9}, {%10,%11,%12,%13};"
        : "=f"(d.x), "=f"(d.y), "=f"(d.z), "=f"(d.w)
        : "r"(a0), "r"(a1), "r"(a2), "r"(a3), "r"(b0), "r"(b1),
          "f"(c0), "f"(c1), "f"(c2), "f"(c3));
    return d;
}

#define NROWS 65536
// exact-fit persistent grid: 148 SMs x 3 CTAs x 4 warps
#define HMMA_BLOCKS 444
#define HMMA_WARPS  (HMMA_BLOCKS * 4)   // 1776

// padded stride for lane-indexed shared tables (bank-conflict-free)
#define PSTR 36

// ---------------- SINGLE fused kernel ----------------
// Main MLP on the tensor pipe (fp16, 32 MMA/row, phase-interleaved m-chains),
// then the sel-MLP + gating tail fused in per row (warp-cooperative, fp32,
// shared-memory weight tables). One launch; no scratch; no constant bank.
__global__ __launch_bounds__(128, 3)
void dqv_fused_kernel(const float* __restrict__ x,
                      const int*   __restrict__ selp,
                      const float* __restrict__ oW1, const float* __restrict__ ob1,
                      const float* __restrict__ oW2, const float* __restrict__ ob2,
                      const float* __restrict__ oW3, const float* __restrict__ ob3,
                      const float* __restrict__ sW1, const float* __restrict__ sb1,
                      const float* __restrict__ sW2, const float* __restrict__ sb2,
                      const float* __restrict__ sW3, const float* __restrict__ sb3,
                      const float* __restrict__ gW1, const float* __restrict__ gb1,
                      const float* __restrict__ gW2, const float* __restrict__ gb2,
                      float* __restrict__ out_q)
{
    // ---- shared tables for the fused tail ----
    __shared__ __align__(16) float s_sW1t[32 * 4];    // [n][d]
    __shared__             float s_sb1[32];
    __shared__ __align__(16) float s_sW2t[32 * PSTR]; // [n][i] padded
    __shared__             float s_sb2[32];
    __shared__             float s_sW3[32 * 16];      // [j][k]
    __shared__             float s_sb3[16];
    __shared__ __align__(16) float s_gW1t[32 * PSTR]; // [m][c] padded
    __shared__             float s_gb1[32];
    __shared__             float s_gW2[64];
    __shared__             float s_gb2[2];

    const int tid = threadIdx.x;
    for (int idx = tid; idx < 128; idx += 128) {
        int d = idx >> 5, n = idx & 31;
        s_sW1t[n * 4 + d] = sW1[idx];
    }
    for (int idx = tid; idx < 1024; idx += 128) {
        int i = idx >> 5, j = idx & 31;
        s_sW2t[j * PSTR + i] = sW2[idx];
        s_gW1t[j * PSTR + i] = gW1[idx];
    }
    for (int idx = tid; idx < 512; idx += 128) s_sW3[idx] = sW3[idx];
    if (tid < 32) { s_sb1[tid] = sb1[tid]; s_sb2[tid] = sb2[tid]; s_gb1[tid] = gb1[tid]; }
    if (tid >= 32 && tid < 48)   s_sb3[tid - 32]  = sb3[tid - 32];
    if (tid >= 48 && tid < 112)  s_gW2[tid - 48]  = gW2[tid - 48];
    if (tid >= 112 && tid < 114) s_gb2[tid - 112] = gb2[tid - 112];
    __syncthreads();

    const int lane  = tid & 31;
    const int warp  = tid >> 5;
    const int gwarp = blockIdx.x * 4 + warp;      // 0..1775
    const int g  = lane >> 2;                      // 0..7
    const int tc = lane & 3;                       // 0..3
    const int sel = selp[0];
    const uint Z = 0u;

    // ---- B fragments (single fp16, loaded once per persistent warp) ----
    uint B1[4];
    #pragma unroll
    for (int n = 0; n < 4; ++n) {
        float wa = 0.0f, wb = 0.0f;
        if (tc < 2) {
            wa = oW1[(2 * tc) * 32 + 8 * n + g];
            wb = oW1[(2 * tc + 1) * 32 + 8 * n + g];
        }
        B1[n] = pack_f16(wa, wb);
    }
    uint B2[4][2][2];
    #pragma unroll
    for (int n = 0; n < 4; ++n) {
        #pragma unroll
        for (int ks = 0; ks < 2; ++ks) {
            int c  = 8 * n + g;
            int k0 = 16 * ks + 2 * tc;
            B2[n][ks][0] = pack_f16(oW2[k0 * 32 + c],       oW2[(k0 + 1) * 32 + c]);
            B2[n][ks][1] = pack_f16(oW2[(k0 + 8) * 32 + c], oW2[(k0 + 9) * 32 + c]);
        }
    }
    uint B3[2][2][2];
    #pragma unroll
    for (int n = 0; n < 2; ++n) {
        #pragma unroll
        for (int ks = 0; ks < 2; ++ks) {
            int c  = 8 * n + g;
            int k0 = 16 * ks + 2 * tc;
            B3[n][ks][0] = pack_f16(oW3[k0 * 16 + c],       oW3[(k0 + 1) * 16 + c]);
            B3[n][ks][1] = pack_f16(oW3[(k0 + 8) * 16 + c], oW3[(k0 + 9) * 16 + c]);
        }
    }
    float2 bz1[4], bz2[4], bz3[2];
    #pragma unroll
    for (int n = 0; n < 4; ++n) {
        bz1[n] = *reinterpret_cast<const float2*>(ob1 + 8 * n + 2 * tc);
        bz2[n] = *reinterpret_cast<const float2*>(ob2 + 8 * n + 2 * tc);
    }
    #pragma unroll
    for (int n = 0; n < 2; ++n)
        bz3[n] = *reinterpret_cast<const float2*>(ob3 + 8 * n + 2 * tc);

    // per-lane x offsets (within a row of 128 floats)
    const int offA0 = (g) * 4 + (tc & 1) * 2;
    const int offB0 = (8 + g) * 4 + (tc & 1) * 2;
    const int offA1 = (16 + g) * 4 + (tc & 1) * 2;
    const int offB1 = (24 + g) * 4 + (tc & 1) * 2;

    // grid-stride over rows; software prefetch of the next iteration's row
    int row = gwarp;
    {
        const float* xr = x + (size_t)row * 128;
        float2 nA0 = *reinterpret_cast<const float2*>(xr + offA0);
        float2 nB0 = *reinterpret_cast<const float2*>(xr + offB0);
        float2 nA1 = *reinterpret_cast<const float2*>(xr + offA1);
        float2 nB1 = *reinterpret_cast<const float2*>(xr + offB1);

        while (row < NROWS) {
            const int nrow = row + HMMA_WARPS;
            float2 cA[2] = { nA0, nA1 };
            float2 cB[2] = { nB0, nB1 };
            if (nrow < NROWS) {
                const float* xn = x + (size_t)nrow * 128;
                nA0 = *reinterpret_cast<const float2*>(xn + offA0);
                nB0 = *reinterpret_cast<const float2*>(xn + offB0);
                nA1 = *reinterpret_cast<const float2*>(xn + offA1);
                nB1 = *reinterpret_cast<const float2*>(xn + offB1);
            }

            // ---- phase-interleaved: both m-chains advance together ----
            uint a0[2], a1[2];
            #pragma unroll
            for (int m = 0; m < 2; ++m) {
                a0[m] = pack_f16(cA[m].x, cA[m].y);
                a1[m] = pack_f16(cB[m].x, cB[m].y);
            }

            // G1 (both m): bias via separate C
            float4 D1[2][4];
            #pragma unroll
            for (int m = 0; m < 2; ++m)
                #pragma unroll
                for (int n = 0; n < 4; ++n)
                    D1[m][n] = mma_f16_c(a0[m], a1[m], Z, Z, B1[n], Z,
                                         bz1[n].x, bz1[n].y, bz1[n].x, bz1[n].y);

            // G2 ks=0 (both m)
            uint A[2][4];
            #pragma unroll
            for (int m = 0; m < 2; ++m) {
                A[m][0] = packrelu_f16(D1[m][0].x, D1[m][0].y);
                A[m][1] = packrelu_f16(D1[m][0].z, D1[m][0].w);
                A[m][2] = packrelu_f16(D1[m][1].x, D1[m][1].y);
                A[m][3] = packrelu_f16(D1[m][1].z, D1[m][1].w);
            }
            float4 D2[2][4];
            #pragma unroll
            for (int m = 0; m < 2; ++m)
                #pragma unroll
                for (int n = 0; n < 4; ++n)
                    D2[m][n] = mma_f16_c(A[m][0], A[m][1], A[m][2], A[m][3],
                                         B2[n][0][0], B2[n][0][1],
                                         bz2[n].x, bz2[n].y, bz2[n].x, bz2[n].y);
            // G2 ks=1 (both m)
            #pragma unroll
            for (int m = 0; m < 2; ++m) {
                A[m][0] = packrelu_f16(D1[m][2].x, D1[m][2].y);
                A[m][1] = packrelu_f16(D1[m][2].z, D1[m][2].w);
                A[m][2] = packrelu_f16(D1[m][3].x, D1[m][3].y);
                A[m][3] = packrelu_f16(D1[m][3].z, D1[m][3].w);
            }
            #pragma unroll
            for (int m = 0; m < 2; ++m)
                #pragma unroll
                for (int n = 0; n < 4; ++n)
                    mma_f16(D2[m][n], A[m][0], A[m][1], A[m][2], A[m][3],
                            B2[n][1][0], B2[n][1][1]);

            // G3 ks=0 (both m)
            #pragma unroll
            for (int m = 0; m < 2; ++m) {
                A[m][0] = packrelu_f16(D2[m][0].x, D2[m][0].y);
                A[m][1] = packrelu_f16(D2[m][0].z, D2[m][0].w);
                A[m][2] = packrelu_f16(D2[m][1].x, D2[m][1].y);
                A[m][3] = packrelu_f16(D2[m][1].z, D2[m][1].w);
            }
            float4 D3[2][2];
            #pragma unroll
            for (int m = 0; m < 2; ++m)
                #pragma unroll
                for (int n = 0; n < 2; ++n)
                    D3[m][n] = mma_f16_c(A[m][0], A[m][1], A[m][2], A[m][3],
                                         B3[n][0][0], B3[n][0][1],
                                         bz3[n].x, bz3[n].y, bz3[n].x, bz3[n].y);
            // G3 ks=1 (both m)
            #pragma unroll
            for (int m = 0; m < 2; ++m) {
                A[m][0] = packrelu_f16(D2[m][2].x, D2[m][2].y);
                A[m][1] = packrelu_f16(D2[m][2].z, D2[m][2].w);
                A[m][2] = packrelu_f16(D2[m][3].x, D2[m][3].y);
                A[m][3] = packrelu_f16(D2[m][3].z, D2[m][3].w);
            }
            #pragma unroll
            for (int m = 0; m < 2; ++m)
                #pragma unroll
                for (int n = 0; n < 2; ++n)
                    mma_f16(D3[m][n], A[m][0], A[m][1], A[m][2], A[m][3],
                            B3[n][1][0], B3[n][1][1]);

            // epilogue: relu, mask selected agent, accumulate over m
            float v00 = 0.f, v01 = 0.f, v10 = 0.f, v11 = 0.f;
            #pragma unroll
            for (int m = 0; m < 2; ++m) {
                float mk0 = (m * 16 + g == sel) ? 0.0f : 1.0f;
                float mk1 = (m * 16 + 8 + g == sel) ? 0.0f : 1.0f;
                v00 += relu_(D3[m][0].x) * mk0 + relu_(D3[m][0].z) * mk1;
                v01 += relu_(D3[m][0].y) * mk0 + relu_(D3[m][0].w) * mk1;
                v10 += relu_(D3[m][1].x) * mk0 + relu_(D3[m][1].z) * mk1;
                v11 += relu_(D3[m][1].y) * mk0 + relu_(D3[m][1].w) * mk1;
            }

            ull p0 = pk2(v00, v01);
            ull p1 = pk2(v10, v11);
            #pragma unroll
            for (int off = 4; off < 32; off <<= 1) {
                p0 = fadd2(p0, __shfl_xor_sync(FULL, p0, off));
                p1 = fadd2(p1, __shfl_xor_sync(FULL, p1, off));
            }
            // p0 = sum_other cols (2tc, 2tc+1); p1 = cols (8+2tc, 8+2tc+1)

            // ---- fused tail (warp-cooperative, fp32, shared tables) ----
            // gather all 16 sum_other values into every lane
            float so[16];
            #pragma unroll
            for (int t = 0; t < 4; ++t) {
                ull q0g = __shfl_sync(FULL, p0, t);   // lane t has tc=t
                ull q1g = __shfl_sync(FULL, p1, t);
                upk2(q0g, so[2 * t], so[2 * t + 1]);
                upk2(q1g, so[8 + 2 * t], so[8 + 2 * t + 1]);
            }

            // selected agent's input (uniform load, L1-resident)
            const float4 xs = *reinterpret_cast<const float4*>(
                x + (size_t)row * 128 + sel * 4);

            // sel layer1: lane = neuron
            float4 w1v = reinterpret_cast<const float4*>(s_sW1t)[lane];
            float sh1 = relu_(fmaf(xs.x, w1v.x, fmaf(xs.y, w1v.y,
                              fmaf(xs.z, w1v.z, fmaf(xs.w, w1v.w, s_sb1[lane])))));

            // sel layer2: lane = neuron, shuffle activations
            float a2 = s_sb2[lane];
            #pragma unroll
            for (int q = 0; q < 8; ++q) {
                float4 w = *reinterpret_cast<const float4*>(s_sW2t + lane * PSTR + 4 * q);
                a2 = fmaf(__shfl_sync(FULL, sh1, 4 * q + 0), w.x, a2);
                a2 = fmaf(__shfl_sync(FULL, sh1, 4 * q + 1), w.y, a2);
                a2 = fmaf(__shfl_sync(FULL, sh1, 4 * q + 2), w.z, a2);
                a2 = fmaf(__shfl_sync(FULL, sh1, 4 * q + 3), w.w, a2);
            }
            const float sh2 = relu_(a2);

            // sel layer3: lanes k and k+16 both compute component k
            const int k15 = lane & 15;
            float a3 = s_sb3[k15];
            #pragma unroll
            for (int j = 0; j < 32; ++j)
                a3 = fmaf(__shfl_sync(FULL, sh2, j), s_sW3[j * 16 + k15], a3);
            const float sel_out = relu_(a3);

            // gating hidden: lane = neuron m; concat = [sel_out(16), sum_other(16)]
            float ag = s_gb1[lane];
            #pragma unroll
            for (int mq = 0; mq < 4; ++mq) {
                float4 w = *reinterpret_cast<const float4*>(s_gW1t + lane * PSTR + 4 * mq);
                ag = fmaf(__shfl_sync(FULL, sel_out, 4 * mq + 0), w.x, ag);
                ag = fmaf(__shfl_sync(FULL, sel_out, 4 * mq + 1), w.y, ag);
                ag = fmaf(__shfl_sync(FULL, sel_out, 4 * mq + 2), w.z, ag);
                ag = fmaf(__shfl_sync(FULL, sel_out, 4 * mq + 3), w.w, ag);
            }
            #pragma unroll
            for (int mq = 0; mq < 4; ++mq) {
                float4 w = *reinterpret_cast<const float4*>(s_gW1t + lane * PSTR + 16 + 4 * mq);
                ag = fmaf(so[4 * mq + 0], w.x, ag);
                ag = fmaf(so[4 * mq + 1], w.y, ag);
                ag = fmaf(so[4 * mq + 2], w.z, ag);
                ag = fmaf(so[4 * mq + 3], w.w, ag);
            }
            const float hg = relu_(ag);

            float q0 = hg * s_gW2[lane * 2 + 0];
            float q1 = hg * s_gW2[lane * 2 + 1];
            #pragma unroll
            for (int off = 16; off; off >>= 1) {
                q0 += __shfl_xor_sync(FULL, q0, off);
                q1 += __shfl_xor_sync(FULL, q1, off);
            }

            if (lane == 0) {
                int act = (int)xs.w;
                act = act < 0 ? 0 : (act > 1 ? 1 : act);
                out_q[row] = act ? (q1 + s_gb2[1]) : (q0 + s_gb2[0]);
            }

            row = nrow;
        }
    }
}

extern "C" void kernel_launch(void* const* d_in, const int* in_sizes, int n_in,
                              void* d_out, int out_size)
{
    (void)in_sizes; (void)n_in; (void)out_size;

    // single fused kernel: exact-fit persistent grid (148 SMs x 3 CTAs)
    dqv_fused_kernel<<<HMMA_BLOCKS, 128>>>(
        (const float*)d_in[0],  (const int*)d_in[1],
        (const float*)d_in[2],  (const float*)d_in[3],
        (const float*)d_in[4],  (const float*)d_in[5],
        (const float*)d_in[6],  (const float*)d_in[7],
        (const float*)d_in[8],  (const float*)d_in[9],
        (const float*)d_in[10], (const float*)d_in[11],
        (const float*)d_in[12], (const float*)d_in[13],
        (const float*)d_in[14], (const float*)d_in[15],
        (const float*)d_in[16], (const float*)d_in[17],
        (float*)d_out);
}

// round 17
// speedup vs baseline: 1.3353x; 1.3353x over previous
#include <cuda_runtime.h>
#include <cuda_fp16.h>

#define FULL 0xffffffffu
typedef unsigned long long ull;
typedef unsigned int uint;

__device__ __forceinline__ float relu_(float v) { return fmaxf(v, 0.0f); }

__device__ __forceinline__ ull ffma2(ull a, ull b, ull c) {
    ull d; asm("fma.rn.f32x2 %0, %1, %2, %3;" : "=l"(d) : "l"(a), "l"(b), "l"(c)); return d;
}
__device__ __forceinline__ ull fadd2(ull a, ull b) {
    ull d; asm("add.rn.f32x2 %0, %1, %2;" : "=l"(d) : "l"(a), "l"(b)); return d;
}
__device__ __forceinline__ ull pk2(float lo, float hi) {
    ull r; asm("mov.b64 %0, {%1, %2};" : "=l"(r) : "f"(lo), "f"(hi)); return r;
}
__device__ __forceinline__ void upk2(ull v, float& lo, float& hi) {
    asm("mov.b64 {%0, %1}, %2;" : "=f"(lo), "=f"(hi) : "l"(v));
}
__device__ __forceinline__ ull relu2(ull v) {
    float lo, hi; upk2(v, lo, hi);
    return pk2(fmaxf(lo, 0.0f), fmaxf(hi, 0.0f));
}
__device__ __forceinline__ float hadd2(ull v) {
    float lo, hi; upk2(v, lo, hi); return lo + hi;
}

// fp16x2 pack (e0 -> lower 16 bits)
__device__ __forceinline__ uint pack_f16(float e0, float e1) {
    __half2 h = __floats2half2_rn(e0, e1);
    return *reinterpret_cast<uint*>(&h);
}
// relu in the fp16x2 domain
__device__ __forceinline__ uint hrelu2(uint v) {
    uint r; asm("max.f16x2 %0, %1, %2;" : "=r"(r) : "r"(v), "r"(0u)); return r;
}
// f16x2 -> 2 floats
__device__ __forceinline__ float2 h2f2(uint v) {
    __half2 h = *reinterpret_cast<__half2*>(&v);
    return __half22float2(h);
}

// m16n8k16 fp16 MMA with fp16 accumulators, in-place.
__device__ __forceinline__ void mma_h(uint2& d, uint a0, uint a1, uint a2, uint a3,
                                      uint b0, uint b1) {
    asm volatile(
        "mma.sync.aligned.m16n8k16.row.col.f16.f16.f16.f16 "
        "{%0,%1}, {%2,%3,%4,%5}, {%6,%7}, {%0,%1};"
        : "+r"(d.x), "+r"(d.y)
        : "r"(a0), "r"(a1), "r"(a2), "r"(a3), "r"(b0), "r"(b1));
}
// fp16-acc MMA with SEPARATE C (bias folded in, no init movs).
__device__ __forceinline__ uint2 mma_h_c(uint a0, uint a1, uint a2, uint a3,
                                         uint b0, uint b1, uint c0, uint c1) {
    uint2 d;
    asm volatile(
        "mma.sync.aligned.m16n8k16.row.col.f16.f16.f16.f16 "
        "{%0,%1}, {%2,%3,%4,%5}, {%6,%7}, {%8,%9};"
        : "=r"(d.x), "=r"(d.y)
        : "r"(a0), "r"(a1), "r"(a2), "r"(a3), "r"(b0), "r"(b1),
          "r"(c0), "r"(c1));
    return d;
}

// ---------------- constant blob (tail weights; layout as rounds 7-15) ----------------
#define CW_TOTAL 4624
__constant__ __align__(16) float c_w[CW_TOTAL];
__device__   __align__(16) float g_blob[CW_TOTAL];

#define NROWS 65536
__device__ __align__(16) ull g_sum[NROWS * 8];

// exact-fit persistent grid at occ-4: 148 SMs x 4 CTAs x 4 warps
#define HMMA_BLOCKS 592
#define HMMA_WARPS  (HMMA_BLOCKS * 4)   // 2368

__global__ void pack_kernel(const float* __restrict__ oW1, const float* __restrict__ ob1,
                            const float* __restrict__ oW2, const float* __restrict__ ob2,
                            const float* __restrict__ oW3, const float* __restrict__ ob3,
                            const float* __restrict__ sW1, const float* __restrict__ sb1,
                            const float* __restrict__ sW2, const float* __restrict__ sb2,
                            const float* __restrict__ sW3, const float* __restrict__ sb3,
                            const float* __restrict__ gW1, const float* __restrict__ gb1,
                            const float* __restrict__ gW2, const float* __restrict__ gb2)
{
    const int gt = blockIdx.x * 256 + threadIdx.x;   // 0..2047
    if (gt < 128) {
        int tp = gt >> 3, d = (gt >> 1) & 3, e = gt & 1;
        g_blob[gt]        = oW1[d * 32 + 2 * tp + e];
        g_blob[1744 + gt] = sW1[d * 32 + 2 * tp + e];
    }
    if (gt >= 128 && gt < 160) {
        int t = gt - 128;
        g_blob[128 + t]  = ob1[t];
        g_blob[1184 + t] = ob2[t];
        g_blob[1872 + t] = sb1[t];
        g_blob[2928 + t] = sb2[t];
        g_blob[4512 + t] = gb1[t];
    }
    if (gt >= 160 && gt < 176) { g_blob[1728 + gt - 160] = ob3[gt - 160]; }
    if (gt >= 176 && gt < 192) { g_blob[3472 + gt - 176] = sb3[gt - 176]; }
    if (gt >= 192 && gt < 256) { g_blob[4544 + gt - 192] = gW2[gt - 192]; }
    if (gt >= 256 && gt < 258) { g_blob[4608 + gt - 256] = gb2[gt - 256]; }
    if (gt < 1024) {
        int j = gt >> 5, i = gt & 31;
        g_blob[160  + j * 32 + i] = oW2[i * 32 + j];
        g_blob[1904 + j * 32 + i] = sW2[i * 32 + j];
        g_blob[3488 + j * 32 + i] = gW1[i * 32 + j];
    }
    if (gt >= 1024 && gt < 1536) {
        int idx = gt - 1024;
        g_blob[1216 + idx] = oW3[idx];
        g_blob[2960 + idx] = sW3[idx];
    }
}

// ---------------- Kernel A: other-agent MLP, fp16-accumulator HMMA ----------------
// f16 D-fragment == next layer's A-fragment (relu = one max.f16x2; zero cvts).
// Accumulator regs halved -> occ-4; both m-chains phase-interleaved.
__global__ __launch_bounds__(128, 4)
void hmma_kernel(const float* __restrict__ x,
                 const int*   __restrict__ selp,
                 const float* __restrict__ oW1, const float* __restrict__ ob1,
                 const float* __restrict__ oW2, const float* __restrict__ ob2,
                 const float* __restrict__ oW3, const float* __restrict__ ob3)
{
    const int lane  = threadIdx.x & 31;
    const int warp  = threadIdx.x >> 5;
    const int gwarp = blockIdx.x * 4 + warp;      // 0..2367
    const int g  = lane >> 2;                      // 0..7
    const int tc = lane & 3;                       // 0..3
    const int sel = selp[0];
    const uint Z = 0u;

    // ---- B fragments (fp16) ----
    uint B1[4];
    #pragma unroll
    for (int n = 0; n < 4; ++n) {
        float wa = 0.0f, wb = 0.0f;
        if (tc < 2) {
            wa = oW1[(2 * tc) * 32 + 8 * n + g];
            wb = oW1[(2 * tc + 1) * 32 + 8 * n + g];
        }
        B1[n] = pack_f16(wa, wb);
    }
    uint B2[4][2][2];
    #pragma unroll
    for (int n = 0; n < 4; ++n) {
        #pragma unroll
        for (int ks = 0; ks < 2; ++ks) {
            int c  = 8 * n + g;
            int k0 = 16 * ks + 2 * tc;
            B2[n][ks][0] = pack_f16(oW2[k0 * 32 + c],       oW2[(k0 + 1) * 32 + c]);
            B2[n][ks][1] = pack_f16(oW2[(k0 + 8) * 32 + c], oW2[(k0 + 9) * 32 + c]);
        }
    }
    uint B3[2][2][2];
    #pragma unroll
    for (int n = 0; n < 2; ++n) {
        #pragma unroll
        for (int ks = 0; ks < 2; ++ks) {
            int c  = 8 * n + g;
            int k0 = 16 * ks + 2 * tc;
            B3[n][ks][0] = pack_f16(oW3[k0 * 16 + c],       oW3[(k0 + 1) * 16 + c]);
            B3[n][ks][1] = pack_f16(oW3[(k0 + 8) * 16 + c], oW3[(k0 + 9) * 16 + c]);
        }
    }
    // bias fragments in fp16x2 (rows g and g+8 share bias -> one reg per tile)
    uint bc1[4], bc2[4], bc3[2];
    #pragma unroll
    for (int n = 0; n < 4; ++n) {
        bc1[n] = pack_f16(ob1[8 * n + 2 * tc], ob1[8 * n + 2 * tc + 1]);
        bc2[n] = pack_f16(ob2[8 * n + 2 * tc], ob2[8 * n + 2 * tc + 1]);
    }
    #pragma unroll
    for (int n = 0; n < 2; ++n)
        bc3[n] = pack_f16(ob3[8 * n + 2 * tc], ob3[8 * n + 2 * tc + 1]);

    // per-lane x offsets (within a row of 128 floats)
    const int offA0 = (g) * 4 + (tc & 1) * 2;
    const int offB0 = (8 + g) * 4 + (tc & 1) * 2;
    const int offA1 = (16 + g) * 4 + (tc & 1) * 2;
    const int offB1 = (24 + g) * 4 + (tc & 1) * 2;

    // grid-stride over rows; software prefetch of the next iteration's row
    int row = gwarp;
    const float* xr = x + (size_t)row * 128;
    float2 nA0 = *reinterpret_cast<const float2*>(xr + offA0);
    float2 nB0 = *reinterpret_cast<const float2*>(xr + offB0);
    float2 nA1 = *reinterpret_cast<const float2*>(xr + offA1);
    float2 nB1 = *reinterpret_cast<const float2*>(xr + offB1);

    while (row < NROWS) {
        const int nrow = row + HMMA_WARPS;
        float2 cA[2] = { nA0, nA1 };
        float2 cB[2] = { nB0, nB1 };
        if (nrow < NROWS) {
            const float* xn = x + (size_t)nrow * 128;
            nA0 = *reinterpret_cast<const float2*>(xn + offA0);
            nB0 = *reinterpret_cast<const float2*>(xn + offB0);
            nA1 = *reinterpret_cast<const float2*>(xn + offA1);
            nB1 = *reinterpret_cast<const float2*>(xn + offB1);
        }

        // ---- phase-interleaved m-chains, fp16 end-to-end ----
        uint a0[2], a1[2];
        #pragma unroll
        for (int m = 0; m < 2; ++m) {
            a0[m] = pack_f16(cA[m].x, cA[m].y);
            a1[m] = pack_f16(cB[m].x, cB[m].y);
        }

        // G1 (both m): 1 MMA per n-tile, bias via C
        uint2 D1[2][4];
        #pragma unroll
        for (int m = 0; m < 2; ++m)
            #pragma unroll
            for (int n = 0; n < 4; ++n)
                D1[m][n] = mma_h_c(a0[m], a1[m], Z, Z, B1[n], Z, bc1[n], bc1[n]);

        // G2 ks=0 (both m): A = relu(D1 tiles 0,1) directly
        uint2 D2[2][4];
        #pragma unroll
        for (int m = 0; m < 2; ++m) {
            uint A0 = hrelu2(D1[m][0].x), A1 = hrelu2(D1[m][0].y);
            uint A2 = hrelu2(D1[m][1].x), A3 = hrelu2(D1[m][1].y);
            #pragma unroll
            for (int n = 0; n < 4; ++n)
                D2[m][n] = mma_h_c(A0, A1, A2, A3, B2[n][0][0], B2[n][0][1],
                                   bc2[n], bc2[n]);
        }
        // G2 ks=1 (both m): A = relu(D1 tiles 2,3)
        #pragma unroll
        for (int m = 0; m < 2; ++m) {
            uint A0 = hrelu2(D1[m][2].x), A1 = hrelu2(D1[m][2].y);
            uint A2 = hrelu2(D1[m][3].x), A3 = hrelu2(D1[m][3].y);
            #pragma unroll
            for (int n = 0; n < 4; ++n)
                mma_h(D2[m][n], A0, A1, A2, A3, B2[n][1][0], B2[n][1][1]);
        }

        // G3 ks=0 (both m)
        uint2 D3[2][2];
        #pragma unroll
        for (int m = 0; m < 2; ++m) {
            uint A0 = hrelu2(D2[m][0].x), A1 = hrelu2(D2[m][0].y);
            uint A2 = hrelu2(D2[m][1].x), A3 = hrelu2(D2[m][1].y);
            #pragma unroll
            for (int n = 0; n < 2; ++n)
                D3[m][n] = mma_h_c(A0, A1, A2, A3, B3[n][0][0], B3[n][0][1],
                                   bc3[n], bc3[n]);
        }
        // G3 ks=1 (both m)
        #pragma unroll
        for (int m = 0; m < 2; ++m) {
            uint A0 = hrelu2(D2[m][2].x), A1 = hrelu2(D2[m][2].y);
            uint A2 = hrelu2(D2[m][3].x), A3 = hrelu2(D2[m][3].y);
            #pragma unroll
            for (int n = 0; n < 2; ++n)
                mma_h(D3[m][n], A0, A1, A2, A3, B3[n][1][0], B3[n][1][1]);
        }

        // epilogue: relu (f16), convert fp32, mask selected agent, accumulate
        float v00 = 0.f, v01 = 0.f, v10 = 0.f, v11 = 0.f;
        #pragma unroll
        for (int m = 0; m < 2; ++m) {
            float mk0 = (m * 16 + g == sel) ? 0.0f : 1.0f;
            float mk1 = (m * 16 + 8 + g == sel) ? 0.0f : 1.0f;
            float2 r00 = h2f2(hrelu2(D3[m][0].x));   // row g,   cols 2tc..+1
            float2 r01 = h2f2(hrelu2(D3[m][0].y));   // row g+8
            float2 r10 = h2f2(hrelu2(D3[m][1].x));   // row g,   cols 8+2tc..+1
            float2 r11 = h2f2(hrelu2(D3[m][1].y));   // row g+8
            v00 += r00.x * mk0 + r01.x * mk1;
            v01 += r00.y * mk0 + r01.y * mk1;
            v10 += r10.x * mk0 + r11.x * mk1;
            v11 += r10.y * mk0 + r11.y * mk1;
        }

        ull p0 = pk2(v00, v01);
        ull p1 = pk2(v10, v11);
        #pragma unroll
        for (int off = 4; off < 32; off <<= 1) {
            p0 = fadd2(p0, __shfl_xor_sync(FULL, p0, off));
            p1 = fadd2(p1, __shfl_xor_sync(FULL, p1, off));
        }
        if (lane < 4) {
            g_sum[(size_t)row * 8 + tc]     = p0;
            g_sum[(size_t)row * 8 + 4 + tc] = p1;
        }

        row = nrow;
    }
}

// ---------------- Kernel B: tail (unchanged, full fp32, constant bank) -------------
__global__ __launch_bounds__(256)
void tail_kernel(const float* __restrict__ x,
                 const int*   __restrict__ selp,
                 float* __restrict__ out_q)
{
    const int row = blockIdx.x * 256 + threadIdx.x;
    const int sel = selp[0];

    const float4 xs = reinterpret_cast<const float4*>(x)[row * 32 + sel];

    ull so_p[8];
    {
        const ulonglong2* src = reinterpret_cast<const ulonglong2*>(g_sum + (size_t)row * 8);
        #pragma unroll
        for (int r = 0; r < 4; ++r) {
            ulonglong2 v = src[r];
            so_p[2 * r + 0] = v.x;
            so_p[2 * r + 1] = v.y;
        }
    }

    ull xd0 = pk2(xs.x, xs.x), xd1 = pk2(xs.y, xs.y);
    ull xd2 = pk2(xs.z, xs.z), xd3 = pk2(xs.w, xs.w);
    ull h1[16];
    {
        const ulonglong2* w1 = reinterpret_cast<const ulonglong2*>(c_w + 1744);
        const ull* b1 = reinterpret_cast<const ull*>(c_w + 1872);
        #pragma unroll
        for (int t = 0; t < 16; ++t) {
            ulonglong2 wA = w1[2 * t + 0];
            ulonglong2 wB = w1[2 * t + 1];
            ull a = ffma2(xd0, wA.x, b1[t]);
            a = ffma2(xd1, wA.y, a);
            a = ffma2(xd2, wB.x, a);
            a = ffma2(xd3, wB.y, a);
            h1[t] = relu2(a);
        }
    }

    ull acc3[8];
    {
        const ull* b3 = reinterpret_cast<const ull*>(c_w + 3472);
        #pragma unroll
        for (int t = 0; t < 8; ++t) acc3[t] = b3[t];
    }
    #pragma unroll 4
    for (int j = 0; j < 32; ++j) {
        ull a = 0ull;
        const ulonglong2* w2 = reinterpret_cast<const ulonglong2*>(c_w + 1904 + j * 32);
        #pragma unroll
        for (int q = 0; q < 8; ++q) {
            ulonglong2 w = w2[q];
            a = ffma2(h1[2 * q + 0], w.x, a);
            a = ffma2(h1[2 * q + 1], w.y, a);
        }
        float s = relu_(hadd2(a) + c_w[2928 + j]);
        ull p = pk2(s, s);
        const ulonglong2* w3 = reinterpret_cast<const ulonglong2*>(c_w + 2960 + j * 16);
        #pragma unroll
        for (int r = 0; r < 4; ++r) {
            ulonglong2 w = w3[r];
            acc3[2 * r + 0] = ffma2(p, w.x, acc3[2 * r + 0]);
            acc3[2 * r + 1] = ffma2(p, w.y, acc3[2 * r + 1]);
        }
    }
    #pragma unroll
    for (int t = 0; t < 8; ++t) acc3[t] = relu2(acc3[t]);

    float q0 = 0.0f, q1 = 0.0f;
    #pragma unroll 4
    for (int m = 0; m < 32; ++m) {
        ull a = 0ull;
        const ulonglong2* wg = reinterpret_cast<const ulonglong2*>(c_w + 3488 + m * 32);
        #pragma unroll
        for (int q = 0; q < 4; ++q) {
            ulonglong2 w = wg[q];
            a = ffma2(acc3[2 * q + 0], w.x, a);
            a = ffma2(acc3[2 * q + 1], w.y, a);
        }
        #pragma unroll
        for (int q = 0; q < 4; ++q) {
            ulonglong2 w = wg[4 + q];
            a = ffma2(so_p[2 * q + 0], w.x, a);
            a = ffma2(so_p[2 * q + 1], w.y, a);
        }
        float gg = relu_(hadd2(a) + c_w[4512 + m]);
        q0 = fmaf(gg, c_w[4544 + 2 * m + 0], q0);
        q1 = fmaf(gg, c_w[4544 + 2 * m + 1], q1);
    }

    int act = (int)xs.w;
    act = act < 0 ? 0 : (act > 1 ? 1 : act);
    out_q[row] = act ? (q1 + c_w[4609]) : (q0 + c_w[4608]);
}

extern "C" void kernel_launch(void* const* d_in, const int* in_sizes, int n_in,
                              void* d_out, int out_size)
{
    (void)in_sizes; (void)n_in; (void)out_size;

    static cudaStream_t s2 = nullptr;
    static cudaEvent_t evFork = nullptr, evJoin = nullptr;
    if (!s2) {
        cudaStreamCreateWithFlags(&s2, cudaStreamNonBlocking);
        cudaEventCreateWithFlags(&evFork, cudaEventDisableTiming);
        cudaEventCreateWithFlags(&evJoin, cudaEventDisableTiming);
    }

    void* dst = nullptr;
    void* src = nullptr;
    cudaGetSymbolAddress(&dst, c_w);
    cudaGetSymbolAddress(&src, g_blob);

    // Fork: pack + memcpy on s2, overlapped with hmma on the main stream.
    cudaEventRecord(evFork, 0);
    cudaStreamWaitEvent(s2, evFork, 0);

    pack_kernel<<<8, 256, 0, s2>>>(
        (const float*)d_in[2],  (const float*)d_in[3],
        (const float*)d_in[4],  (const float*)d_in[5],
        (const float*)d_in[6],  (const float*)d_in[7],
        (const float*)d_in[8],  (const float*)d_in[9],
        (const float*)d_in[10], (const float*)d_in[11],
        (const float*)d_in[12], (const float*)d_in[13],
        (const float*)d_in[14], (const float*)d_in[15],
        (const float*)d_in[16], (const float*)d_in[17]);
    cudaMemcpyAsync(dst, src, CW_TOTAL * sizeof(float),
                    cudaMemcpyDeviceToDevice, s2);
    cudaEventRecord(evJoin, s2);

    // Kernel A (fp16-acc tensor pipe): exact-fit persistent grid at occ-4.
    hmma_kernel<<<HMMA_BLOCKS, 128>>>(
        (const float*)d_in[0], (const int*)d_in[1],
        (const float*)d_in[2], (const float*)d_in[3],
        (const float*)d_in[4], (const float*)d_in[5],
        (const float*)d_in[6], (const float*)d_in[7]);

    // Join: tail needs both g_sum (main stream) and c_w (s2).
    cudaStreamWaitEvent(0, evJoin, 0);
    tail_kernel<<<256, 256>>>((const float*)d_in[0], (const int*)d_in[1],
                              (float*)d_out);
}